// round 10
// baseline (speedup 1.0000x reference)
#include <cuda_runtime.h>
#include <cstddef>
#include <cstdint>

#define N_NODES 100000
#define N_EDGES 1600000

// ---------------- scratch (static device arrays; no cudaMalloc) ------------
__device__ float g_agg1[(size_t)N_NODES * 128];   // segment_mean(x)
__device__ float g_t2[(size_t)N_NODES * 64];      // h1_relu @ W_neigh2
__device__ float g_hself2[(size_t)N_NODES * 64];  // h1_relu @ W_self2 + b2
__device__ int   g_deg[N_NODES];                  // zero-init; re-zeroed by scan each run
__device__ int   g_off[N_NODES + 1];
__device__ int   g_cur[N_NODES];
__device__ int   g_ssrc[N_EDGES];

// ---------------- CSR build ------------------------------------------------
__global__ void count_deg_kernel(const int* __restrict__ dst) {
    int e = blockIdx.x * blockDim.x + threadIdx.x;
    if (e < N_EDGES) atomicAdd(&g_deg[dst[e]], 1);
}

// single-block exclusive scan over 100k degrees; also re-zeroes g_deg so the
// next invocation's count_deg starts from zero (deterministic across replays).
__global__ void scan_offsets_kernel() {
    __shared__ int part[1024];
    const int tid = threadIdx.x;
    const int CH = (N_NODES + 1023) / 1024;  // 98
    int beg = tid * CH;
    int end = beg + CH; if (end > N_NODES) end = N_NODES;
    if (beg > N_NODES) beg = N_NODES;

    int s = 0;
    for (int i = beg; i < end; i++) s += g_deg[i];
    part[tid] = s;
    __syncthreads();
    for (int off = 1; off < 1024; off <<= 1) {
        int v = (tid >= off) ? part[tid - off] : 0;
        __syncthreads();
        part[tid] += v;
        __syncthreads();
    }
    int run = (tid == 0) ? 0 : part[tid - 1];  // exclusive prefix
    for (int i = beg; i < end; i++) {
        int d = g_deg[i];
        g_off[i] = run;
        g_cur[i] = run;
        g_deg[i] = 0;          // reset for next invocation
        run += d;
    }
    if (tid == 1023) g_off[N_NODES] = run;
}

__global__ void fill_csr_kernel(const int* __restrict__ src,
                                const int* __restrict__ dst) {
    int e = blockIdx.x * blockDim.x + threadIdx.x;
    if (e < N_EDGES) {
        int p = atomicAdd(&g_cur[dst[e]], 1);
        g_ssrc[p] = src[e];
    }
}

// ---------------- gather: agg[n] = mean of x[src rows], D=128 --------------
__global__ __launch_bounds__(256)
void gather_mean128(const float* __restrict__ x, float* __restrict__ agg) {
    int warp = (blockIdx.x * blockDim.x + threadIdx.x) >> 5;
    int lane = threadIdx.x & 31;
    if (warp >= N_NODES) return;
    const int n   = warp;
    const int beg = g_off[n];
    const int end = g_off[n + 1];
    const int lo4 = lane * 4;

    float4 acc = make_float4(0.f, 0.f, 0.f, 0.f);
    int e = beg;
    for (; e + 3 < end; e += 4) {
        int s0 = g_ssrc[e];
        int s1 = g_ssrc[e + 1];
        int s2 = g_ssrc[e + 2];
        int s3 = g_ssrc[e + 3];
        float4 v0 = *reinterpret_cast<const float4*>(x + (size_t)s0 * 128 + lo4);
        float4 v1 = *reinterpret_cast<const float4*>(x + (size_t)s1 * 128 + lo4);
        float4 v2 = *reinterpret_cast<const float4*>(x + (size_t)s2 * 128 + lo4);
        float4 v3 = *reinterpret_cast<const float4*>(x + (size_t)s3 * 128 + lo4);
        acc.x += (v0.x + v1.x) + (v2.x + v3.x);
        acc.y += (v0.y + v1.y) + (v2.y + v3.y);
        acc.z += (v0.z + v1.z) + (v2.z + v3.z);
        acc.w += (v0.w + v1.w) + (v2.w + v3.w);
    }
    for (; e < end; e++) {
        int s0 = g_ssrc[e];
        float4 v0 = *reinterpret_cast<const float4*>(x + (size_t)s0 * 128 + lo4);
        acc.x += v0.x; acc.y += v0.y; acc.z += v0.z; acc.w += v0.w;
    }
    float inv = 1.0f / fmaxf((float)(end - beg), 1.0f);
    float4 o = make_float4(acc.x * inv, acc.y * inv, acc.z * inv, acc.w * inv);
    *reinterpret_cast<float4*>(agg + (size_t)n * 128 + lo4) = o;
}

// ---------------- 3xTF32 mma helpers ---------------------------------------
__device__ __forceinline__ float tf32_rn(float v) {
    uint32_t o;
    asm("cvt.rna.tf32.f32 %0, %1;" : "=r"(o) : "f"(v));
    return __uint_as_float(o);
}

__device__ __forceinline__ void mma_tf32(float* c,
                                         uint32_t a0, uint32_t a1, uint32_t a2, uint32_t a3,
                                         uint32_t b0, uint32_t b1) {
    asm volatile(
        "mma.sync.aligned.m16n8k8.row.col.f32.tf32.tf32.f32 "
        "{%0,%1,%2,%3}, {%4,%5,%6,%7}, {%8,%9}, {%0,%1,%2,%3};\n"
        : "+f"(c[0]), "+f"(c[1]), "+f"(c[2]), "+f"(c[3])
        : "r"(a0), "r"(a1), "r"(a2), "r"(a3), "r"(b0), "r"(b1));
}

// ---------------- fused layer-1 GEMM ---------------------------------------
// h1[M,128] = [x | agg] @ [Wself(128x128); Wneigh(128x128)] + b1
// (K = 256). Writes h1 and relu(h1).
__global__ __launch_bounds__(256, 2)
void gemm1_fused(const float* __restrict__ x,
                 const float* __restrict__ agg,
                 const float* __restrict__ Wself,
                 const float* __restrict__ Wneigh,
                 const float* __restrict__ bias,
                 float* __restrict__ h1,
                 float* __restrict__ h1r,
                 int M) {
    constexpr int BM = 128, BN = 128, BK = 16, K = 256, D = 128;
    __shared__ float2 As2[BK][BM + 2];
    __shared__ float2 Bs2[BK][BN + 2];

    const int tid  = threadIdx.x;
    const int lane = tid & 31;
    const int warp = tid >> 5;
    const int g    = lane >> 2;
    const int tg   = lane & 3;
    const int warpM = (warp >> 1) * 32;
    const int warpN = (warp & 1) * 64;
    const int brow = blockIdx.x * BM;

    const int aRow = tid >> 1;
    const int aCol = (tid & 1) * 8;
    const bool aOK = (brow + aRow) < M;
    const size_t aRowOff = (size_t)(brow + aRow) * D + aCol;

    const int bK = tid >> 4;          // 0..15
    const int bC = (tid & 15) * 8;    // 0..120

    float acc[2][8][4];
#pragma unroll
    for (int mt = 0; mt < 2; mt++)
#pragma unroll
        for (int nt = 0; nt < 8; nt++)
#pragma unroll
            for (int q = 0; q < 4; q++) acc[mt][nt][q] = 0.f;

    for (int k0 = 0; k0 < K; k0 += BK) {
        const float* aSrc = (k0 < D) ? x : agg;
        const int kloc = k0 & (D - 1);
#pragma unroll
        for (int h = 0; h < 2; h++) {
            float4 v = make_float4(0.f, 0.f, 0.f, 0.f);
            if (aOK) v = *reinterpret_cast<const float4*>(aSrc + aRowOff + kloc + h * 4);
            float vv[4] = {v.x, v.y, v.z, v.w};
#pragma unroll
            for (int j = 0; j < 4; j++) {
                float hi = tf32_rn(vv[j]);
                float lo = tf32_rn(vv[j] - hi);
                As2[aCol + h * 4 + j][aRow] = make_float2(hi, lo);
            }
        }
        {
            int kg = k0 + bK;
            const float* bSrc = (kg < D) ? (Wself + (size_t)kg * D)
                                         : (Wneigh + (size_t)(kg - D) * D);
#pragma unroll
            for (int h = 0; h < 2; h++) {
                float4 v = *reinterpret_cast<const float4*>(bSrc + bC + h * 4);
                float vv[4] = {v.x, v.y, v.z, v.w};
#pragma unroll
                for (int j = 0; j < 4; j++) {
                    float hi = tf32_rn(vv[j]);
                    float lo = tf32_rn(vv[j] - hi);
                    Bs2[bK][bC + h * 4 + j] = make_float2(hi, lo);
                }
            }
        }
        __syncthreads();

#pragma unroll
        for (int kk = 0; kk < BK; kk += 8) {
            float2 af[2][4];
#pragma unroll
            for (int mt = 0; mt < 2; mt++) {
                int m = warpM + mt * 16 + g;
                af[mt][0] = As2[kk + tg][m];
                af[mt][1] = As2[kk + tg][m + 8];
                af[mt][2] = As2[kk + tg + 4][m];
                af[mt][3] = As2[kk + tg + 4][m + 8];
            }
#pragma unroll
            for (int nt = 0; nt < 8; nt++) {
                int n = warpN + nt * 8 + g;
                float2 bf0 = Bs2[kk + tg][n];
                float2 bf1 = Bs2[kk + tg + 4][n];
                uint32_t bh0 = __float_as_uint(bf0.x), bl0 = __float_as_uint(bf0.y);
                uint32_t bh1 = __float_as_uint(bf1.x), bl1 = __float_as_uint(bf1.y);
#pragma unroll
                for (int mt = 0; mt < 2; mt++) {
                    uint32_t ah0 = __float_as_uint(af[mt][0].x);
                    uint32_t ah1 = __float_as_uint(af[mt][1].x);
                    uint32_t ah2 = __float_as_uint(af[mt][2].x);
                    uint32_t ah3 = __float_as_uint(af[mt][3].x);
                    uint32_t al0 = __float_as_uint(af[mt][0].y);
                    uint32_t al1 = __float_as_uint(af[mt][1].y);
                    uint32_t al2 = __float_as_uint(af[mt][2].y);
                    uint32_t al3 = __float_as_uint(af[mt][3].y);
                    mma_tf32(acc[mt][nt], ah0, ah1, ah2, ah3, bh0, bh1);
                    mma_tf32(acc[mt][nt], ah0, ah1, ah2, ah3, bl0, bl1);
                    mma_tf32(acc[mt][nt], al0, al1, al2, al3, bh0, bh1);
                }
            }
        }
        __syncthreads();
    }

#pragma unroll
    for (int mt = 0; mt < 2; mt++) {
#pragma unroll
        for (int nt = 0; nt < 8; nt++) {
            int gcol = warpN + nt * 8 + 2 * tg;
            float bb0 = bias[gcol];
            float bb1 = bias[gcol + 1];
            int r0 = brow + warpM + mt * 16 + g;
            int r1 = r0 + 8;
            if (r0 < M) {
                float2 o = make_float2(acc[mt][nt][0] + bb0, acc[mt][nt][1] + bb1);
                *reinterpret_cast<float2*>(h1 + (size_t)r0 * D + gcol) = o;
                float2 r = make_float2(fmaxf(o.x, 0.f), fmaxf(o.y, 0.f));
                *reinterpret_cast<float2*>(h1r + (size_t)r0 * D + gcol) = r;
            }
            if (r1 < M) {
                float2 o = make_float2(acc[mt][nt][2] + bb0, acc[mt][nt][3] + bb1);
                *reinterpret_cast<float2*>(h1 + (size_t)r1 * D + gcol) = o;
                float2 r = make_float2(fmaxf(o.x, 0.f), fmaxf(o.y, 0.f));
                *reinterpret_cast<float2*>(h1r + (size_t)r1 * D + gcol) = r;
            }
        }
    }
}

// ---------------- layer-2 dual GEMM ----------------------------------------
// hs2 = h1r @ Wself2 + b2 ; t2 = h1r @ Wneigh2   (n0 = 64, K = 128)
__global__ __launch_bounds__(256, 2)
void gemm2_dual(const float* __restrict__ A,
                const float* __restrict__ B0,
                const float* __restrict__ B1,
                const float* __restrict__ bias,
                float* __restrict__ out0,
                float* __restrict__ out1,
                int M, int n0) {
    constexpr int BM = 128, BN = 128, BK = 16, K = 128;
    __shared__ float2 As2[BK][BM + 2];
    __shared__ float2 Bs2[BK][BN + 2];

    const int tid  = threadIdx.x;
    const int lane = tid & 31;
    const int warp = tid >> 5;
    const int g    = lane >> 2;
    const int tg   = lane & 3;
    const int warpM = (warp >> 1) * 32;
    const int warpN = (warp & 1) * 64;
    const int brow = blockIdx.x * BM;

    const int aRow = tid >> 1;
    const int aCol = (tid & 1) * 8;
    const bool aOK = (brow + aRow) < M;
    const float* aBase = A + (size_t)(brow + aRow) * K + aCol;

    const int bK = tid >> 4;
    const int bC = (tid & 15) * 8;
    const float* bHalf = (bC < n0) ? B0 : B1;
    const int   bCol   = (bC < n0) ? bC : (bC - n0);

    float acc[2][8][4];
#pragma unroll
    for (int mt = 0; mt < 2; mt++)
#pragma unroll
        for (int nt = 0; nt < 8; nt++)
#pragma unroll
            for (int q = 0; q < 4; q++) acc[mt][nt][q] = 0.f;

    for (int k0 = 0; k0 < K; k0 += BK) {
#pragma unroll
        for (int h = 0; h < 2; h++) {
            float4 v = make_float4(0.f, 0.f, 0.f, 0.f);
            if (aOK) v = *reinterpret_cast<const float4*>(aBase + k0 + h * 4);
            float vv[4] = {v.x, v.y, v.z, v.w};
#pragma unroll
            for (int j = 0; j < 4; j++) {
                float hi = tf32_rn(vv[j]);
                float lo = tf32_rn(vv[j] - hi);
                As2[aCol + h * 4 + j][aRow] = make_float2(hi, lo);
            }
        }
#pragma unroll
        for (int h = 0; h < 2; h++) {
            float4 v = *reinterpret_cast<const float4*>(
                bHalf + (size_t)(k0 + bK) * n0 + bCol + h * 4);
            float vv[4] = {v.x, v.y, v.z, v.w};
#pragma unroll
            for (int j = 0; j < 4; j++) {
                float hi = tf32_rn(vv[j]);
                float lo = tf32_rn(vv[j] - hi);
                Bs2[bK][bC + h * 4 + j] = make_float2(hi, lo);
            }
        }
        __syncthreads();

#pragma unroll
        for (int kk = 0; kk < BK; kk += 8) {
            float2 af[2][4];
#pragma unroll
            for (int mt = 0; mt < 2; mt++) {
                int m = warpM + mt * 16 + g;
                af[mt][0] = As2[kk + tg][m];
                af[mt][1] = As2[kk + tg][m + 8];
                af[mt][2] = As2[kk + tg + 4][m];
                af[mt][3] = As2[kk + tg + 4][m + 8];
            }
#pragma unroll
            for (int nt = 0; nt < 8; nt++) {
                int n = warpN + nt * 8 + g;
                float2 bf0 = Bs2[kk + tg][n];
                float2 bf1 = Bs2[kk + tg + 4][n];
                uint32_t bh0 = __float_as_uint(bf0.x), bl0 = __float_as_uint(bf0.y);
                uint32_t bh1 = __float_as_uint(bf1.x), bl1 = __float_as_uint(bf1.y);
#pragma unroll
                for (int mt = 0; mt < 2; mt++) {
                    uint32_t ah0 = __float_as_uint(af[mt][0].x);
                    uint32_t ah1 = __float_as_uint(af[mt][1].x);
                    uint32_t ah2 = __float_as_uint(af[mt][2].x);
                    uint32_t ah3 = __float_as_uint(af[mt][3].x);
                    uint32_t al0 = __float_as_uint(af[mt][0].y);
                    uint32_t al1 = __float_as_uint(af[mt][1].y);
                    uint32_t al2 = __float_as_uint(af[mt][2].y);
                    uint32_t al3 = __float_as_uint(af[mt][3].y);
                    mma_tf32(acc[mt][nt], ah0, ah1, ah2, ah3, bh0, bh1);
                    mma_tf32(acc[mt][nt], ah0, ah1, ah2, ah3, bl0, bl1);
                    mma_tf32(acc[mt][nt], al0, al1, al2, al3, bh0, bh1);
                }
            }
        }
        __syncthreads();
    }

#pragma unroll
    for (int mt = 0; mt < 2; mt++) {
#pragma unroll
        for (int nt = 0; nt < 8; nt++) {
            int gcol = warpN + nt * 8 + 2 * tg;
            int r0 = brow + warpM + mt * 16 + g;
            int r1 = r0 + 8;
            if (gcol < n0) {
                float bb0 = bias[gcol];
                float bb1 = bias[gcol + 1];
                if (r0 < M)
                    *reinterpret_cast<float2*>(out0 + (size_t)r0 * n0 + gcol) =
                        make_float2(acc[mt][nt][0] + bb0, acc[mt][nt][1] + bb1);
                if (r1 < M)
                    *reinterpret_cast<float2*>(out0 + (size_t)r1 * n0 + gcol) =
                        make_float2(acc[mt][nt][2] + bb0, acc[mt][nt][3] + bb1);
            } else {
                int cc = gcol - n0;
                if (r0 < M)
                    *reinterpret_cast<float2*>(out1 + (size_t)r0 * n0 + cc) =
                        make_float2(acc[mt][nt][0], acc[mt][nt][1]);
                if (r1 < M)
                    *reinterpret_cast<float2*>(out1 + (size_t)r1 * n0 + cc) =
                        make_float2(acc[mt][nt][2], acc[mt][nt][3]);
            }
        }
    }
}

// ---------------- layer-2 gather+combine: warp per dst node (D=64) ---------
__global__ __launch_bounds__(256)
void gather_combine2(const float* __restrict__ hself,
                     const float* __restrict__ t,
                     float* __restrict__ out_a,
                     float* __restrict__ out_b) {
    int warp = (blockIdx.x * blockDim.x + threadIdx.x) >> 5;
    int lane = threadIdx.x & 31;
    if (warp >= N_NODES) return;
    const int n   = warp;
    const int beg = g_off[n];
    const int end = g_off[n + 1];
    const int lo2 = lane * 2;

    float2 acc = make_float2(0.f, 0.f);
    int e = beg;
    for (; e + 3 < end; e += 4) {
        int s0 = g_ssrc[e];
        int s1 = g_ssrc[e + 1];
        int s2 = g_ssrc[e + 2];
        int s3 = g_ssrc[e + 3];
        float2 v0 = *reinterpret_cast<const float2*>(t + (size_t)s0 * 64 + lo2);
        float2 v1 = *reinterpret_cast<const float2*>(t + (size_t)s1 * 64 + lo2);
        float2 v2 = *reinterpret_cast<const float2*>(t + (size_t)s2 * 64 + lo2);
        float2 v3 = *reinterpret_cast<const float2*>(t + (size_t)s3 * 64 + lo2);
        acc.x += (v0.x + v1.x) + (v2.x + v3.x);
        acc.y += (v0.y + v1.y) + (v2.y + v3.y);
    }
    for (; e < end; e++) {
        int s0 = g_ssrc[e];
        float2 v0 = *reinterpret_cast<const float2*>(t + (size_t)s0 * 64 + lo2);
        acc.x += v0.x; acc.y += v0.y;
    }
    float inv = 1.0f / fmaxf((float)(end - beg), 1.0f);
    float2 hs = *reinterpret_cast<const float2*>(hself + (size_t)n * 64 + lo2);
    float2 h2 = make_float2(hs.x + acc.x * inv, hs.y + acc.y * inv);
    *reinterpret_cast<float2*>(out_a + (size_t)n * 64 + lo2) = h2;
    *reinterpret_cast<float2*>(out_b + (size_t)n * 64 + lo2) = h2;
}

// ---------------- launch ---------------------------------------------------
extern "C" void kernel_launch(void* const* d_in, const int* in_sizes, int n_in,
                              void* d_out, int out_size) {
    const float* x        = (const float*)d_in[0];
    const float* W_self1  = (const float*)d_in[1];
    const float* W_neigh1 = (const float*)d_in[2];
    const float* b1       = (const float*)d_in[3];
    const float* W_self2  = (const float*)d_in[4];
    const float* W_neigh2 = (const float*)d_in[5];
    const float* b2       = (const float*)d_in[6];
    const int*   src      = (const int*)d_in[7];
    const int*   dst      = (const int*)d_in[8];

    float* out = (float*)d_out;
    float* out_h2a = out;                                      // 100000*64
    float* out_h1  = out + (size_t)N_NODES * 64;               // 100000*128
    float* out_h1r = out + (size_t)N_NODES * (64 + 128);       // 100000*128
    float* out_h2b = out + (size_t)N_NODES * (64 + 128 + 128); // 100000*64

    float* agg1 = nullptr, *t2 = nullptr, *hs2 = nullptr;
    cudaGetSymbolAddress((void**)&agg1, g_agg1);
    cudaGetSymbolAddress((void**)&t2,   g_t2);
    cudaGetSymbolAddress((void**)&hs2,  g_hself2);

    // launch 0..2: CSR build (g_deg re-zeroed inside scan for next run)
    count_deg_kernel<<<(N_EDGES + 255) / 256, 256>>>(dst);
    scan_offsets_kernel<<<1, 1024>>>();
    fill_csr_kernel<<<(N_EDGES + 255) / 256, 256>>>(src, dst);

    // launch 3 (ncu capture slot): the big gather — agg1 = segment_mean(x)
    int gblocks = (N_NODES * 32 + 255) / 256;  // one warp per node
    gather_mean128<<<gblocks, 256>>>(x, agg1);

    // launch 4: fused layer-1 GEMM (K=256) -> h1, h1_relu
    gemm1_fused<<<(N_NODES + 127) / 128, 256>>>(x, agg1, W_self1, W_neigh1, b1,
                                                out_h1, out_h1r, N_NODES);

    // launch 5: layer-2 dual GEMM on h1_relu -> hs2, t2
    gemm2_dual<<<(N_NODES + 127) / 128, 256>>>(out_h1r, W_self2, W_neigh2, b2,
                                               hs2, t2, N_NODES, 64);

    // launch 6: layer-2 gather + combine
    gather_combine2<<<gblocks, 256>>>(hs2, t2, out_h2a, out_h2b);
}

// round 11
// speedup vs baseline: 1.4441x; 1.4441x over previous
#include <cuda_runtime.h>
#include <cstddef>
#include <cstdint>

#define N_NODES 100000
#define N_EDGES 1600000
#define NB_SCAN 391            // ceil(100000 / 256)

// ---------------- scratch (static device arrays; no cudaMalloc) ------------
__device__ float g_t1[(size_t)N_NODES * 128];     // x @ W_neigh1
__device__ float g_hself1[(size_t)N_NODES * 128]; // x @ W_self1 + b1
__device__ float g_t2[(size_t)N_NODES * 64];      // h1_relu @ W_neigh2
__device__ float g_hself2[(size_t)N_NODES * 64];  // h1_relu @ W_self2 + b2
__device__ int   g_deg[N_NODES];                  // zero-init; re-zeroed by scatter
__device__ int   g_off[N_NODES + 1];
__device__ int   g_cur[N_NODES];
__device__ int   g_ssrc[N_EDGES];
__device__ int   g_bsum[512];                     // per-block degree sums
__device__ int   g_bpref[512];                    // exclusive prefix of block sums

// ---------------- CSR build (parallel two-level scan) -----------------------
__global__ void count_deg_kernel(const int* __restrict__ dst) {
    int e = blockIdx.x * blockDim.x + threadIdx.x;
    if (e < N_EDGES) atomicAdd(&g_deg[dst[e]], 1);
}

// per-block sums of g_deg (coalesced)
__global__ __launch_bounds__(256)
void block_sum_kernel() {
    __shared__ int sh[8];
    int i = blockIdx.x * 256 + threadIdx.x;
    int v = (i < N_NODES) ? g_deg[i] : 0;
    // warp reduce
    for (int o = 16; o > 0; o >>= 1) v += __shfl_down_sync(0xffffffffu, v, o);
    if ((threadIdx.x & 31) == 0) sh[threadIdx.x >> 5] = v;
    __syncthreads();
    if (threadIdx.x < 8) {
        int s = sh[threadIdx.x];
        for (int o = 4; o > 0; o >>= 1) s += __shfl_down_sync(0xffu, s, o);
        if (threadIdx.x == 0) g_bsum[blockIdx.x] = s;
    }
}

// single-block scan over NB_SCAN block sums (tiny)
__global__ __launch_bounds__(512)
void block_scan_kernel() {
    __shared__ int sh[512];
    int t = threadIdx.x;
    int v = (t < NB_SCAN) ? g_bsum[t] : 0;
    sh[t] = v;
    __syncthreads();
    for (int o = 1; o < 512; o <<= 1) {
        int u = (t >= o) ? sh[t - o] : 0;
        __syncthreads();
        sh[t] += u;
        __syncthreads();
    }
    if (t < NB_SCAN) g_bpref[t] = sh[t] - v;   // exclusive
}

// per-block local scan + scatter offsets; re-zeroes g_deg for next invocation
__global__ __launch_bounds__(256)
void scatter_offsets_kernel() {
    __shared__ int sh[256];
    int t = threadIdx.x;
    int i = blockIdx.x * 256 + t;
    int v = (i < N_NODES) ? g_deg[i] : 0;
    sh[t] = v;
    __syncthreads();
    for (int o = 1; o < 256; o <<= 1) {
        int u = (t >= o) ? sh[t - o] : 0;
        __syncthreads();
        sh[t] += u;
        __syncthreads();
    }
    if (i < N_NODES) {
        int off = g_bpref[blockIdx.x] + sh[t] - v;  // global exclusive prefix
        g_off[i] = off;
        g_cur[i] = off;
        g_deg[i] = 0;                               // reset for next run
    }
    if (blockIdx.x == 0 && t == 0) g_off[N_NODES] = N_EDGES;
}

__global__ void fill_csr_kernel(const int* __restrict__ src,
                                const int* __restrict__ dst) {
    int e = blockIdx.x * blockDim.x + threadIdx.x;
    if (e < N_EDGES) {
        int p = atomicAdd(&g_cur[dst[e]], 1);
        g_ssrc[p] = src[e];
    }
}

// ---------------- 3xTF32 tensor-core dual-output GEMM ----------------------
// C[M, 2*n0] = A[M,128] @ [B0 | B1]; cols < n0 -> out0 (+bias), else out1.
__device__ __forceinline__ float tf32_rn(float v) {
    uint32_t o;
    asm("cvt.rna.tf32.f32 %0, %1;" : "=r"(o) : "f"(v));
    return __uint_as_float(o);
}

__device__ __forceinline__ void mma_tf32(float* c,
                                         uint32_t a0, uint32_t a1, uint32_t a2, uint32_t a3,
                                         uint32_t b0, uint32_t b1) {
    asm volatile(
        "mma.sync.aligned.m16n8k8.row.col.f32.tf32.tf32.f32 "
        "{%0,%1,%2,%3}, {%4,%5,%6,%7}, {%8,%9}, {%0,%1,%2,%3};\n"
        : "+f"(c[0]), "+f"(c[1]), "+f"(c[2]), "+f"(c[3])
        : "r"(a0), "r"(a1), "r"(a2), "r"(a3), "r"(b0), "r"(b1));
}

__global__ __launch_bounds__(256, 2)
void tf32_dual_gemm(const float* __restrict__ A,
                    const float* __restrict__ B0,
                    const float* __restrict__ B1,
                    const float* __restrict__ bias,
                    float* __restrict__ out0,
                    float* __restrict__ out1,
                    int M, int n0) {
    constexpr int BM = 128, BN = 128, BK = 16, K = 128;
    __shared__ float2 As2[BK][BM + 2];
    __shared__ float2 Bs2[BK][BN + 2];

    const int tid  = threadIdx.x;
    const int lane = tid & 31;
    const int warp = tid >> 5;
    const int g    = lane >> 2;
    const int tg   = lane & 3;
    const int warpM = (warp >> 1) * 32;
    const int warpN = (warp & 1) * 64;
    const int brow = blockIdx.x * BM;
    const int bcol = blockIdx.y * BN;

    const int aRow = tid >> 1;
    const int aCol = (tid & 1) * 8;
    const bool aOK = (brow + aRow) < M;
    const float* aBase = A + (size_t)(brow + aRow) * K + aCol;

    const int bK = tid >> 4;
    const int bC = (tid & 15) * 8;
    const int bGC = bcol + bC;
    const float* bHalf = (bGC < n0) ? B0 : B1;
    const int   bCol   = (bGC < n0) ? bGC : (bGC - n0);

    float acc[2][8][4];
#pragma unroll
    for (int mt = 0; mt < 2; mt++)
#pragma unroll
        for (int nt = 0; nt < 8; nt++)
#pragma unroll
            for (int q = 0; q < 4; q++) acc[mt][nt][q] = 0.f;

    for (int k0 = 0; k0 < K; k0 += BK) {
#pragma unroll
        for (int h = 0; h < 2; h++) {
            float4 v = make_float4(0.f, 0.f, 0.f, 0.f);
            if (aOK) v = *reinterpret_cast<const float4*>(aBase + k0 + h * 4);
            float vv[4] = {v.x, v.y, v.z, v.w};
#pragma unroll
            for (int j = 0; j < 4; j++) {
                float hi = tf32_rn(vv[j]);
                float lo = tf32_rn(vv[j] - hi);
                As2[aCol + h * 4 + j][aRow] = make_float2(hi, lo);
            }
        }
#pragma unroll
        for (int h = 0; h < 2; h++) {
            float4 v = *reinterpret_cast<const float4*>(
                bHalf + (size_t)(k0 + bK) * n0 + bCol + h * 4);
            float vv[4] = {v.x, v.y, v.z, v.w};
#pragma unroll
            for (int j = 0; j < 4; j++) {
                float hi = tf32_rn(vv[j]);
                float lo = tf32_rn(vv[j] - hi);
                Bs2[bK][bC + h * 4 + j] = make_float2(hi, lo);
            }
        }
        __syncthreads();

#pragma unroll
        for (int kk = 0; kk < BK; kk += 8) {
            float2 af[2][4];
#pragma unroll
            for (int mt = 0; mt < 2; mt++) {
                int m = warpM + mt * 16 + g;
                af[mt][0] = As2[kk + tg][m];
                af[mt][1] = As2[kk + tg][m + 8];
                af[mt][2] = As2[kk + tg + 4][m];
                af[mt][3] = As2[kk + tg + 4][m + 8];
            }
#pragma unroll
            for (int nt = 0; nt < 8; nt++) {
                int n = warpN + nt * 8 + g;
                float2 bf0 = Bs2[kk + tg][n];
                float2 bf1 = Bs2[kk + tg + 4][n];
                uint32_t bh0 = __float_as_uint(bf0.x), bl0 = __float_as_uint(bf0.y);
                uint32_t bh1 = __float_as_uint(bf1.x), bl1 = __float_as_uint(bf1.y);
#pragma unroll
                for (int mt = 0; mt < 2; mt++) {
                    uint32_t ah0 = __float_as_uint(af[mt][0].x);
                    uint32_t ah1 = __float_as_uint(af[mt][1].x);
                    uint32_t ah2 = __float_as_uint(af[mt][2].x);
                    uint32_t ah3 = __float_as_uint(af[mt][3].x);
                    uint32_t al0 = __float_as_uint(af[mt][0].y);
                    uint32_t al1 = __float_as_uint(af[mt][1].y);
                    uint32_t al2 = __float_as_uint(af[mt][2].y);
                    uint32_t al3 = __float_as_uint(af[mt][3].y);
                    mma_tf32(acc[mt][nt], ah0, ah1, ah2, ah3, bh0, bh1);
                    mma_tf32(acc[mt][nt], ah0, ah1, ah2, ah3, bl0, bl1);
                    mma_tf32(acc[mt][nt], al0, al1, al2, al3, bh0, bh1);
                }
            }
        }
        __syncthreads();
    }

#pragma unroll
    for (int mt = 0; mt < 2; mt++) {
#pragma unroll
        for (int nt = 0; nt < 8; nt++) {
            int gcol = bcol + warpN + nt * 8 + 2 * tg;
            int r0 = brow + warpM + mt * 16 + g;
            int r1 = r0 + 8;
            if (gcol < n0) {
                float bb0 = bias ? bias[gcol] : 0.f;
                float bb1 = bias ? bias[gcol + 1] : 0.f;
                if (r0 < M)
                    *reinterpret_cast<float2*>(out0 + (size_t)r0 * n0 + gcol) =
                        make_float2(acc[mt][nt][0] + bb0, acc[mt][nt][1] + bb1);
                if (r1 < M)
                    *reinterpret_cast<float2*>(out0 + (size_t)r1 * n0 + gcol) =
                        make_float2(acc[mt][nt][2] + bb0, acc[mt][nt][3] + bb1);
            } else {
                int cc = gcol - n0;
                if (r0 < M)
                    *reinterpret_cast<float2*>(out1 + (size_t)r0 * n0 + cc) =
                        make_float2(acc[mt][nt][0], acc[mt][nt][1]);
                if (r1 < M)
                    *reinterpret_cast<float2*>(out1 + (size_t)r1 * n0 + cc) =
                        make_float2(acc[mt][nt][2], acc[mt][nt][3]);
            }
        }
    }
}

// ---------------- layer-1 gather+combine: warp per dst node (D=128) --------
__global__ __launch_bounds__(256)
void gather_combine1(const float* __restrict__ hself,
                     const float* __restrict__ t,
                     float* __restrict__ out_h1,
                     float* __restrict__ out_h1r) {
    int warp = (blockIdx.x * blockDim.x + threadIdx.x) >> 5;
    int lane = threadIdx.x & 31;
    if (warp >= N_NODES) return;
    const int n   = warp;
    const int beg = g_off[n];
    const int end = g_off[n + 1];
    const int lo4 = lane * 4;

    float4 acc = make_float4(0.f, 0.f, 0.f, 0.f);
    int e = beg;
    for (; e + 3 < end; e += 4) {
        int s0 = g_ssrc[e];
        int s1 = g_ssrc[e + 1];
        int s2 = g_ssrc[e + 2];
        int s3 = g_ssrc[e + 3];
        float4 v0 = *reinterpret_cast<const float4*>(t + (size_t)s0 * 128 + lo4);
        float4 v1 = *reinterpret_cast<const float4*>(t + (size_t)s1 * 128 + lo4);
        float4 v2 = *reinterpret_cast<const float4*>(t + (size_t)s2 * 128 + lo4);
        float4 v3 = *reinterpret_cast<const float4*>(t + (size_t)s3 * 128 + lo4);
        acc.x += (v0.x + v1.x) + (v2.x + v3.x);
        acc.y += (v0.y + v1.y) + (v2.y + v3.y);
        acc.z += (v0.z + v1.z) + (v2.z + v3.z);
        acc.w += (v0.w + v1.w) + (v2.w + v3.w);
    }
    for (; e < end; e++) {
        int s0 = g_ssrc[e];
        float4 v0 = *reinterpret_cast<const float4*>(t + (size_t)s0 * 128 + lo4);
        acc.x += v0.x; acc.y += v0.y; acc.z += v0.z; acc.w += v0.w;
    }
    float inv = 1.0f / fmaxf((float)(end - beg), 1.0f);
    float4 hs = *reinterpret_cast<const float4*>(hself + (size_t)n * 128 + lo4);
    float4 h1;
    h1.x = hs.x + acc.x * inv;
    h1.y = hs.y + acc.y * inv;
    h1.z = hs.z + acc.z * inv;
    h1.w = hs.w + acc.w * inv;
    *reinterpret_cast<float4*>(out_h1 + (size_t)n * 128 + lo4) = h1;
    float4 r;
    r.x = fmaxf(h1.x, 0.f); r.y = fmaxf(h1.y, 0.f);
    r.z = fmaxf(h1.z, 0.f); r.w = fmaxf(h1.w, 0.f);
    *reinterpret_cast<float4*>(out_h1r + (size_t)n * 128 + lo4) = r;
}

// ---------------- layer-2 gather+combine: warp per dst node (D=64) ---------
__global__ __launch_bounds__(256)
void gather_combine2(const float* __restrict__ hself,
                     const float* __restrict__ t,
                     float* __restrict__ out_a,
                     float* __restrict__ out_b) {
    int warp = (blockIdx.x * blockDim.x + threadIdx.x) >> 5;
    int lane = threadIdx.x & 31;
    if (warp >= N_NODES) return;
    const int n   = warp;
    const int beg = g_off[n];
    const int end = g_off[n + 1];
    const int lo2 = lane * 2;

    float2 acc = make_float2(0.f, 0.f);
    int e = beg;
    for (; e + 3 < end; e += 4) {
        int s0 = g_ssrc[e];
        int s1 = g_ssrc[e + 1];
        int s2 = g_ssrc[e + 2];
        int s3 = g_ssrc[e + 3];
        float2 v0 = *reinterpret_cast<const float2*>(t + (size_t)s0 * 64 + lo2);
        float2 v1 = *reinterpret_cast<const float2*>(t + (size_t)s1 * 64 + lo2);
        float2 v2 = *reinterpret_cast<const float2*>(t + (size_t)s2 * 64 + lo2);
        float2 v3 = *reinterpret_cast<const float2*>(t + (size_t)s3 * 64 + lo2);
        acc.x += (v0.x + v1.x) + (v2.x + v3.x);
        acc.y += (v0.y + v1.y) + (v2.y + v3.y);
    }
    for (; e < end; e++) {
        int s0 = g_ssrc[e];
        float2 v0 = *reinterpret_cast<const float2*>(t + (size_t)s0 * 64 + lo2);
        acc.x += v0.x; acc.y += v0.y;
    }
    float inv = 1.0f / fmaxf((float)(end - beg), 1.0f);
    float2 hs = *reinterpret_cast<const float2*>(hself + (size_t)n * 64 + lo2);
    float2 h2 = make_float2(hs.x + acc.x * inv, hs.y + acc.y * inv);
    *reinterpret_cast<float2*>(out_a + (size_t)n * 64 + lo2) = h2;
    *reinterpret_cast<float2*>(out_b + (size_t)n * 64 + lo2) = h2;
}

// ---------------- launch ---------------------------------------------------
extern "C" void kernel_launch(void* const* d_in, const int* in_sizes, int n_in,
                              void* d_out, int out_size) {
    const float* x        = (const float*)d_in[0];
    const float* W_self1  = (const float*)d_in[1];
    const float* W_neigh1 = (const float*)d_in[2];
    const float* b1       = (const float*)d_in[3];
    const float* W_self2  = (const float*)d_in[4];
    const float* W_neigh2 = (const float*)d_in[5];
    const float* b2       = (const float*)d_in[6];
    const int*   src      = (const int*)d_in[7];
    const int*   dst      = (const int*)d_in[8];

    float* out = (float*)d_out;
    float* out_h2a = out;                                      // 100000*64
    float* out_h1  = out + (size_t)N_NODES * 64;               // 100000*128
    float* out_h1r = out + (size_t)N_NODES * (64 + 128);       // 100000*128
    float* out_h2b = out + (size_t)N_NODES * (64 + 128 + 128); // 100000*64

    float* t1 = nullptr, *hs1 = nullptr, *t2 = nullptr, *hs2 = nullptr;
    cudaGetSymbolAddress((void**)&t1,  g_t1);
    cudaGetSymbolAddress((void**)&hs1, g_hself1);
    cudaGetSymbolAddress((void**)&t2,  g_t2);
    cudaGetSymbolAddress((void**)&hs2, g_hself2);

    // --- CSR build: count + parallel two-level scan + fill ---
    count_deg_kernel<<<(N_EDGES + 255) / 256, 256>>>(dst);
    block_sum_kernel<<<NB_SCAN, 256>>>();
    block_scan_kernel<<<1, 512>>>();
    scatter_offsets_kernel<<<NB_SCAN, 256>>>();
    fill_csr_kernel<<<(N_EDGES + 255) / 256, 256>>>(src, dst);

    // --- layer 1 GEMM: hs1 = x@W_self1+b1 ; t1 = x@W_neigh1 ---
    dim3 g1((N_NODES + 127) / 128, 2);
    tf32_dual_gemm<<<g1, 256>>>(x, W_self1, W_neigh1, b1, hs1, t1, N_NODES, 128);

    int gblocks = (N_NODES * 32 + 255) / 256;  // one warp per node
    gather_combine1<<<gblocks, 256>>>(hs1, t1, out_h1, out_h1r);

    // --- layer 2 GEMM on h1_relu ---
    dim3 g2((N_NODES + 127) / 128, 1);
    tf32_dual_gemm<<<g2, 256>>>(out_h1r, W_self2, W_neigh2, b2, hs2, t2, N_NODES, 64);

    gather_combine2<<<gblocks, 256>>>(hs2, t2, out_h2a, out_h2b);
}